// round 3
// baseline (speedup 1.0000x reference)
#include <cuda_runtime.h>
#include <math.h>

#define D   1024
#define H   8
#define HD  128
#define T   8193
#define SCALE 0.08838834764831845f   // 1/sqrt(128)

// ---- scratch (device globals; no allocation allowed) ----
__device__ float g_q0[D];
__device__ float g_u[H * D];
__device__ float g_scores[H * T];
__device__ float g_m[H];
__device__ float g_rl[H];
__device__ float g_w[H * D];
__device__ float g_attn0[D];
__device__ float g_out0[D];

// K1: zero u/w scratch + q0 = Wq @ cls + bq  (one warp per output row)
__global__ void k1_zero_q0(const float* __restrict__ Wq,
                           const float* __restrict__ bq,
                           const float* __restrict__ cls) {
    int gid = blockIdx.x * blockDim.x + threadIdx.x;
    if (gid < H * D)            g_u[gid] = 0.f;
    else if (gid < 2 * H * D)   g_w[gid - H * D] = 0.f;

    int warp = gid >> 5, lane = gid & 31;   // warp in [0,1024)
    const float4* row4 = reinterpret_cast<const float4*>(Wq) + (size_t)warp * (D / 4);
    const float4* t04  = reinterpret_cast<const float4*>(cls);
    float acc = 0.f;
    #pragma unroll
    for (int k = lane; k < D / 4; k += 32) {
        float4 a = row4[k], b = t04[k];
        acc += a.x * b.x + a.y * b.y + a.z * b.z + a.w * b.w;
    }
    #pragma unroll
    for (int o = 16; o; o >>= 1) acc += __shfl_xor_sync(0xffffffffu, acc, o);
    if (lane == 0) g_q0[warp] = acc + bq[warp];
}

// K2: u[h][j] = sum_d Wk[h*128+d][j] * q0[h*128+d]   (64 blocks, fp32 atomic accumulate)
__global__ void k2_u(const float* __restrict__ Wk) {
    int h = blockIdx.x >> 3, chunk = blockIdx.x & 7;
    int tid = threadIdx.x;                       // 256 threads, each owns 4 j's
    float4 acc = make_float4(0.f, 0.f, 0.f, 0.f);
    #pragma unroll
    for (int r = 0; r < 16; r++) {
        int row = h * HD + chunk * 16 + r;
        float q = g_q0[row];
        float4 wv = reinterpret_cast<const float4*>(Wk)[(size_t)row * (D / 4) + tid];
        acc.x += q * wv.x; acc.y += q * wv.y; acc.z += q * wv.z; acc.w += q * wv.w;
    }
    float* dst = &g_u[h * D + tid * 4];
    atomicAdd(dst + 0, acc.x); atomicAdd(dst + 1, acc.y);
    atomicAdd(dst + 2, acc.z); atomicAdd(dst + 3, acc.w);
}

// K3: scores[h][s] = SCALE * (u_h . token_s). 64 tokens/block, warp handles 8 tokens.
__global__ void k3_scores(const float* __restrict__ x, const float* __restrict__ cls) {
    __shared__ float us[H * D];
    int tid = threadIdx.x;
    for (int i = tid; i < H * D; i += 256) us[i] = g_u[i];
    __syncthreads();

    int warp = tid >> 5, lane = tid & 31;
    int tbase = blockIdx.x * 64 + warp * 8;

    const float* ptr[8];
    #pragma unroll
    for (int tt = 0; tt < 8; tt++) {
        int s = tbase + tt;
        ptr[tt] = (s <= 0 || s >= T) ? cls : x + (size_t)(s - 1) * D;
    }

    float acc[64];
    #pragma unroll
    for (int i = 0; i < 64; i++) acc[i] = 0.f;

    for (int k = 0; k < 32; k++) {
        int j = k * 32 + lane;
        float uv[8];
        #pragma unroll
        for (int h = 0; h < 8; h++) uv[h] = us[h * D + j];
        #pragma unroll
        for (int tt = 0; tt < 8; tt++) {
            float xv = ptr[tt][j];
            #pragma unroll
            for (int h = 0; h < 8; h++) acc[tt * 8 + h] += xv * uv[h];
        }
    }
    #pragma unroll
    for (int o = 16; o; o >>= 1) {
        #pragma unroll
        for (int i = 0; i < 64; i++) acc[i] += __shfl_xor_sync(0xffffffffu, acc[i], o);
    }
    #pragma unroll
    for (int rr = 0; rr < 2; rr++) {
        int r = lane + rr * 32;
        int tt = r >> 3, h = r & 7;
        int s = tbase + tt;
        if (s < T) g_scores[h * T + s] = acc[r] * SCALE;
    }
}

// K4: per-head softmax stats (max, 1/sum)
__global__ void k4_stats() {
    int h = blockIdx.x, tid = threadIdx.x;
    __shared__ float red[1024];
    float mx = -1e30f;
    for (int s = tid; s < T; s += 1024) mx = fmaxf(mx, g_scores[h * T + s]);
    red[tid] = mx; __syncthreads();
    for (int o = 512; o; o >>= 1) { if (tid < o) red[tid] = fmaxf(red[tid], red[tid + o]); __syncthreads(); }
    float m = red[0]; __syncthreads();
    float sum = 0.f;
    for (int s = tid; s < T; s += 1024) sum += expf(g_scores[h * T + s] - m);
    red[tid] = sum; __syncthreads();
    for (int o = 512; o; o >>= 1) { if (tid < o) red[tid] += red[tid + o]; __syncthreads(); }
    if (tid == 0) { g_m[h] = m; g_rl[h] = 1.f / red[0]; }
}

// K5: probs -> A output + w_h = sum_s p[h,s]*token_s (atomic accumulate)
__global__ void k5_pass2(const float* __restrict__ x, const float* __restrict__ cls,
                         float* __restrict__ out) {
    __shared__ float p_sm[64 * 8];
    int tid = threadIdx.x;
    int base = blockIdx.x * 64;

    for (int idx = tid; idx < 512; idx += 256) {
        int tt = idx >> 3, h = idx & 7;
        int s = base + tt;
        float p = 0.f;
        if (s < T) p = expf(g_scores[h * T + s] - g_m[h]) * g_rl[h];
        p_sm[idx] = p;
    }
    __syncthreads();

    if (tid < 64) {
        int s = base + tid;
        if (s >= 1 && s < T) {
            float a = 0.f;
            #pragma unroll
            for (int h = 0; h < 8; h++) a += p_sm[tid * 8 + h];
            out[7 + (s - 1)] = a * 0.125f;            // A
        }
    }

    float acc[8][4];
    #pragma unroll
    for (int h = 0; h < 8; h++) { acc[h][0] = acc[h][1] = acc[h][2] = acc[h][3] = 0.f; }

    for (int tt = 0; tt < 64; tt++) {
        int s = base + tt;
        if (s >= T) break;
        const float* ptr = (s == 0) ? cls : x + (size_t)(s - 1) * D;
        float4 xv = reinterpret_cast<const float4*>(ptr)[tid];
        #pragma unroll
        for (int h = 0; h < 8; h++) {
            float p = p_sm[tt * 8 + h];
            acc[h][0] += p * xv.x; acc[h][1] += p * xv.y;
            acc[h][2] += p * xv.z; acc[h][3] += p * xv.w;
        }
    }
    #pragma unroll
    for (int h = 0; h < 8; h++) {
        float* dst = &g_w[h * D + tid * 4];
        atomicAdd(dst + 0, acc[h][0]); atomicAdd(dst + 1, acc[h][1]);
        atomicAdd(dst + 2, acc[h][2]); atomicAdd(dst + 3, acc[h][3]);
    }
}

// K6: attn0[r] = Wv[r,:] . w[r/128] + bv[r]  (warp per row)
__global__ void k6_attn0(const float* __restrict__ Wv, const float* __restrict__ bv) {
    int gid = blockIdx.x * blockDim.x + threadIdx.x;
    int warp = gid >> 5, lane = gid & 31;
    int h = warp >> 7;
    const float4* row4 = reinterpret_cast<const float4*>(Wv) + (size_t)warp * (D / 4);
    const float4* w4   = reinterpret_cast<const float4*>(&g_w[h * D]);
    float acc = 0.f;
    #pragma unroll
    for (int k = lane; k < D / 4; k += 32) {
        float4 a = row4[k], b = w4[k];
        acc += a.x * b.x + a.y * b.y + a.z * b.z + a.w * b.w;
    }
    #pragma unroll
    for (int o = 16; o; o >>= 1) acc += __shfl_xor_sync(0xffffffffu, acc, o);
    if (lane == 0) g_attn0[warp] = acc + bv[warp];
}

// K7: out0[r] = Wo[r,:] . attn0 + bo[r]  (warp per row)
__global__ void k7_out0(const float* __restrict__ Wo, const float* __restrict__ bo) {
    int gid = blockIdx.x * blockDim.x + threadIdx.x;
    int warp = gid >> 5, lane = gid & 31;
    const float4* row4 = reinterpret_cast<const float4*>(Wo) + (size_t)warp * (D / 4);
    const float4* a4   = reinterpret_cast<const float4*>(g_attn0);
    float acc = 0.f;
    #pragma unroll
    for (int k = lane; k < D / 4; k += 32) {
        float4 a = row4[k], b = a4[k];
        acc += a.x * b.x + a.y * b.y + a.z * b.z + a.w * b.w;
    }
    #pragma unroll
    for (int o = 16; o; o >>= 1) acc += __shfl_xor_sync(0xffffffffu, acc, o);
    if (lane == 0) g_out0[warp] = acc + bo[warp];
}

// K8: logits, softmax, argmax, write scalar outputs
__global__ void k8_final(const float* __restrict__ Wc, const float* __restrict__ bc,
                         float* __restrict__ out) {
    __shared__ float lg[2];
    int tid = threadIdx.x, warp = tid >> 5, lane = tid & 31;
    if (warp < 2) {
        const float4* row4 = reinterpret_cast<const float4*>(Wc) + (size_t)warp * (D / 4);
        const float4* o4   = reinterpret_cast<const float4*>(g_out0);
        float acc = 0.f;
        #pragma unroll
        for (int k = lane; k < D / 4; k += 32) {
            float4 a = row4[k], b = o4[k];
            acc += a.x * b.x + a.y * b.y + a.z * b.z + a.w * b.w;
        }
        #pragma unroll
        for (int o = 16; o; o >>= 1) acc += __shfl_xor_sync(0xffffffffu, acc, o);
        if (lane == 0) lg[warp] = acc + bc[warp];
    }
    __syncthreads();
    if (tid == 0) {
        float l0 = lg[0], l1 = lg[1];
        float mx = fmaxf(l0, l1);
        float e0 = expf(l0 - mx), e1 = expf(l1 - mx);
        float inv = 1.f / (e0 + e1);
        float p0 = e0 * inv, p1 = e1 * inv;
        float yhat = (p1 > p0) ? 1.f : 0.f;   // first-max tie-break like jnp.argmax
        out[0] = l0; out[1] = l1;             // top_instance
        out[2] = p0; out[3] = p1;             // Y_prob
        out[4] = yhat;                        // Y_hat
        out[5] = p0; out[6] = p1;             // y_probs
    }
}

extern "C" void kernel_launch(void* const* d_in, const int* in_sizes, int n_in,
                              void* d_out, int out_size) {
    const float* x   = (const float*)d_in[0];
    const float* cls = (const float*)d_in[1];
    const float* Wq  = (const float*)d_in[2];
    const float* bq  = (const float*)d_in[3];
    const float* Wk  = (const float*)d_in[4];
    // d_in[5] = bk: per-head constant shift of scores -> softmax-invariant, unused
    const float* Wv  = (const float*)d_in[6];
    const float* bv  = (const float*)d_in[7];
    const float* Wo  = (const float*)d_in[8];
    const float* bo  = (const float*)d_in[9];
    const float* Wc  = (const float*)d_in[10];
    const float* bc  = (const float*)d_in[11];
    float* out = (float*)d_out;

    k1_zero_q0<<<128, 256>>>(Wq, bq, cls);
    k2_u<<<64, 256>>>(Wk);
    k3_scores<<<129, 256>>>(x, cls);
    k4_stats<<<8, 1024>>>();
    k5_pass2<<<129, 256>>>(x, cls, out);
    k6_attn0<<<128, 256>>>(Wv, bv);
    k7_out0<<<128, 256>>>(Wo, bo);
    k8_final<<<1, 64>>>(Wc, bc, out);
    (void)in_sizes; (void)n_in; (void)out_size;
}